// round 15
// baseline (speedup 1.0000x reference)
#include <cuda_runtime.h>
#include <cuda_bf16.h>
#include <cstdint>

#define TOKENS 8192
#define DMODEL 2048
#define DFF    8192

// ---------------- device scratch (no allocations allowed) ----------------
struct Scalars {
    unsigned int absmax_x;   // float bits, >= 0
    unsigned int absmax_h;
    double       sum_w1;
    double       sum_w2;
};

__device__ Scalars        g_sc;
__device__ __nv_bfloat16  g_qx [(size_t)TOKENS * DMODEL];   // 32 MB
__device__ __nv_bfloat16  g_w1t[(size_t)DFF    * DMODEL];   // 32 MB
__device__ float          g_h  [(size_t)TOKENS * DFF];      // 256 MB (fp32 h — exact)
__device__ __nv_bfloat16  g_w2t[(size_t)DMODEL * DFF];      // 32 MB

// ---------------- helpers ----------------
__device__ __forceinline__ float gelu_exact(float v) {
    return 0.5f * v * (1.0f + erff(v * 0.70710678118654752440f));
}
__device__ __forceinline__ unsigned smem_u32(const void* p) {
    return (unsigned)__cvta_generic_to_shared(p);
}
__device__ __forceinline__ float amax4(float4 v) {
    return fmaxf(fmaxf(fabsf(v.x), fabsf(v.y)), fmaxf(fabsf(v.z), fabsf(v.w)));
}
__device__ __forceinline__ double asum4(float4 v) {
    return (double)fabsf(v.x) + (double)fabsf(v.y) +
           (double)fabsf(v.z) + (double)fabsf(v.w);
}
__device__ __forceinline__ uint2 quant4(float4 v, float s) {
    float q0 = rintf(fminf(fmaxf(v.x * s, -127.f), 127.f));
    float q1 = rintf(fminf(fmaxf(v.y * s, -127.f), 127.f));
    float q2 = rintf(fminf(fmaxf(v.z * s, -127.f), 127.f));
    float q3 = rintf(fminf(fmaxf(v.w * s, -127.f), 127.f));
    __nv_bfloat162 p0 = __floats2bfloat162_rn(q0, q1);
    __nv_bfloat162 p1 = __floats2bfloat162_rn(q2, q3);
    uint2 o;
    o.x = *reinterpret_cast<unsigned int*>(&p0);
    o.y = *reinterpret_cast<unsigned int*>(&p1);
    return o;
}
__device__ __forceinline__ uint2 tern4(float4 v, float inv) {
    float q0 = rintf(fminf(fmaxf(v.x * inv, -1.f), 1.f));
    float q1 = rintf(fminf(fmaxf(v.y * inv, -1.f), 1.f));
    float q2 = rintf(fminf(fmaxf(v.z * inv, -1.f), 1.f));
    float q3 = rintf(fminf(fmaxf(v.w * inv, -1.f), 1.f));
    __nv_bfloat162 p0 = __floats2bfloat162_rn(q0, q1);
    __nv_bfloat162 p1 = __floats2bfloat162_rn(q2, q3);
    uint2 o;
    o.x = *reinterpret_cast<unsigned int*>(&p0);
    o.y = *reinterpret_cast<unsigned int*>(&p1);
    return o;
}

// ---------------- fused reductions: seg0 absmax(x), seg1 abssum(W1), seg2 abssum(W2)
__global__ void k_reduce3(const float4* __restrict__ x,
                          const float4* __restrict__ W1,
                          const float4* __restrict__ W2,
                          int n4, Scalars* __restrict__ sc) {
    const int seg = blockIdx.y;
    const float4* p = (seg == 0) ? x : (seg == 1) ? W1 : W2;
    const int S = gridDim.x * blockDim.x;
    int i = blockIdx.x * blockDim.x + threadIdx.x;

    if (seg == 0) {
        float m = 0.f;
        for (; i + 3 * S < n4; i += 4 * S) {
            float4 v0 = p[i], v1 = p[i + S], v2 = p[i + 2 * S], v3 = p[i + 3 * S];
            m = fmaxf(m, fmaxf(fmaxf(amax4(v0), amax4(v1)),
                               fmaxf(amax4(v2), amax4(v3))));
        }
        for (; i < n4; i += S) m = fmaxf(m, amax4(p[i]));
        #pragma unroll
        for (int o = 16; o; o >>= 1) m = fmaxf(m, __shfl_xor_sync(0xffffffffu, m, o));
        __shared__ float s[8];
        if ((threadIdx.x & 31) == 0) s[threadIdx.x >> 5] = m;
        __syncthreads();
        if (threadIdx.x == 0) {
            float v = s[0];
            #pragma unroll
            for (int k = 1; k < 8; k++) v = fmaxf(v, s[k]);
            atomicMax(&sc->absmax_x, __float_as_uint(v));
        }
    } else {
        double acc = 0.0;
        for (; i + 3 * S < n4; i += 4 * S) {
            float4 v0 = p[i], v1 = p[i + S], v2 = p[i + 2 * S], v3 = p[i + 3 * S];
            acc += asum4(v0) + asum4(v1) + asum4(v2) + asum4(v3);
        }
        for (; i < n4; i += S) acc += asum4(p[i]);
        #pragma unroll
        for (int o = 16; o; o >>= 1) acc += __shfl_xor_sync(0xffffffffu, acc, o);
        __shared__ double sd[8];
        if ((threadIdx.x & 31) == 0) sd[threadIdx.x >> 5] = acc;
        __syncthreads();
        if (threadIdx.x == 0) {
            double v = sd[0];
            #pragma unroll
            for (int k = 1; k < 8; k++) v += sd[k];
            atomicAdd((seg == 1) ? &sc->sum_w1 : &sc->sum_w2, v);
        }
    }
}

// ---------------- fused prep: seg0 quant(x)->qx, seg1 tern(W1)->w1t, seg2 tern(W2)->w2t
__global__ void k_prep3(const float4* __restrict__ x,
                        const float4* __restrict__ W1,
                        const float4* __restrict__ W2,
                        uint2* __restrict__ qx,
                        uint2* __restrict__ w1t,
                        uint2* __restrict__ w2t,
                        int n4, const Scalars* __restrict__ sc) {
    const int seg = blockIdx.y;
    const float4* in = (seg == 0) ? x : (seg == 1) ? W1 : W2;
    uint2* out = (seg == 0) ? qx : (seg == 1) ? w1t : w2t;
    float s;
    if (seg == 0) s = 127.0f / __uint_as_float(sc->absmax_x);
    else {
        double sum = (seg == 1) ? sc->sum_w1 : sc->sum_w2;
        s = 1.0f / (float)(sum * (1.0 / 16777216.0));
    }
    const int S = gridDim.x * blockDim.x;
    int i = blockIdx.x * blockDim.x + threadIdx.x;
    if (seg == 0) {
        for (; i + 3 * S < n4; i += 4 * S) {
            float4 v0 = in[i], v1 = in[i + S], v2 = in[i + 2 * S], v3 = in[i + 3 * S];
            out[i] = quant4(v0, s);  out[i + S] = quant4(v1, s);
            out[i + 2 * S] = quant4(v2, s);  out[i + 3 * S] = quant4(v3, s);
        }
        for (; i < n4; i += S) out[i] = quant4(in[i], s);
    } else {
        for (; i + 3 * S < n4; i += 4 * S) {
            float4 v0 = in[i], v1 = in[i + S], v2 = in[i + 2 * S], v3 = in[i + 3 * S];
            out[i] = tern4(v0, s);  out[i + S] = tern4(v1, s);
            out[i + 2 * S] = tern4(v2, s);  out[i + 3 * S] = tern4(v3, s);
        }
        for (; i < n4; i += S) out[i] = tern4(in[i], s);
    }
}

// ---------------- bf16 GEMM: C[M,N] = A[M,K] @ B[N,K]^T ----------------
// CTA tile 128x128, BK=64, warp tile 64x64 (2x2 warps), 3-stage pipeline,
// 2 CTAs/SM.
// QA=0: 128 threads; A+B via cp.async (proven R12 config).
// QA=1: 160 threads; warp 4 is a PRODUCER: loads fp32 A (g_h), quantizes
//       (bit-identical to the standalone quant kernel), STSs bf16 into the
//       stage buffer two k-tiles ahead. B via cp.async on warps 0-3.
#define BKE     64                  // K elems per stage
#define SSTR    72                  // smem row stride (elems) = 144 B
#define A_ROWS  128
#define B_ROWS  128
#define STAGE_E ((A_ROWS + B_ROWS) * SSTR)   // 18432 elems
#define STAGES  3
#define SMEM_GB (STAGES * STAGE_E * 2)       // 110592 B

template <int EPI, int QA>
__global__ void __launch_bounds__(QA ? 160 : 128, 2) k_gemm(
    const void* __restrict__ Ain,
    const __nv_bfloat16* __restrict__ B,
    const float* __restrict__ bias,
    float* __restrict__ C,
    int M, int N, int K,
    const double* __restrict__ sump,
    const unsigned int* __restrict__ mxp,
    unsigned int* __restrict__ amax_out)
{
    extern __shared__ __nv_bfloat16 sm[];
    __shared__ float sred[4];

    const int tid  = threadIdx.x;
    const int wid  = tid >> 5;
    const int lane = tid & 31;
    const int bm = blockIdx.y * 128;
    const int bn = blockIdx.x * 128;

    const float mx = __uint_as_float(*mxp);
    const float cf = (float)(*sump * (1.0 / 16777216.0)) * (mx / 127.0f);
    const float qs = 127.0f / mx;   // QA=1 producer quant scale

    const __nv_bfloat16* gA  = (const __nv_bfloat16*)Ain + (size_t)bm * K;
    const float*         gAf = (const float*)Ain + (size_t)bm * K;
    const __nv_bfloat16* gB  = B + (size_t)bn * K;

    // QA=0: A(8)+B(8) 16B chunks per thread (128 threads)
    auto issueAB = [&](int kt, int st) {
        const int k0 = kt * BKE;
        __nv_bfloat16* base = sm + st * STAGE_E;
        #pragma unroll
        for (int i = 0; i < 16; i++) {
            int c = (i & 7) * 128 + tid;
            int row = c >> 3, col = (c & 7) * 8;
            const __nv_bfloat16* src;
            __nv_bfloat16* dst;
            if (i < 8) {
                dst = base + row * SSTR + col;
                src = gA + (size_t)row * K + k0 + col;
            } else {
                dst = base + A_ROWS * SSTR + row * SSTR + col;
                src = gB + (size_t)row * K + k0 + col;
            }
            asm volatile("cp.async.cg.shared.global [%0], [%1], 16;\n"
                         :: "r"(smem_u32(dst)), "l"(src));
        }
        asm volatile("cp.async.commit_group;\n");
    };

    // QA=1: B-only cp.async, warps 0-3 (8 chunks per thread)
    auto issueB = [&](int kt, int st) {
        const int k0 = kt * BKE;
        __nv_bfloat16* base = sm + st * STAGE_E + A_ROWS * SSTR;
        #pragma unroll
        for (int i = 0; i < 8; i++) {
            int c = i * 128 + tid;
            int row = c >> 3, col = (c & 7) * 8;
            asm volatile("cp.async.cg.shared.global [%0], [%1], 16;\n"
                         :: "r"(smem_u32(base + row * SSTR + col)),
                            "l"(gB + (size_t)row * K + k0 + col));
        }
        asm volatile("cp.async.commit_group;\n");
    };

    // QA=1 producer (warp 4): LDG fp32 -> quant -> STS bf16. 2048 float4
    // chunks per stage, 64 per lane, batched 8 for MLP.
    auto produceA = [&](int kt, int st) {
        const int k0 = kt * BKE;
        __nv_bfloat16* base = sm + st * STAGE_E;
        #pragma unroll 1
        for (int ii = 0; ii < 8; ii++) {
            float4 v[8];
            #pragma unroll
            for (int j = 0; j < 8; j++) {
                int c = (ii * 8 + j) * 32 + lane;
                int row = c >> 4, col4 = c & 15;
                v[j] = *reinterpret_cast<const float4*>(
                    gAf + (size_t)row * K + k0 + col4 * 4);
            }
            #pragma unroll
            for (int j = 0; j < 8; j++) {
                int c = (ii * 8 + j) * 32 + lane;
                int row = c >> 4, col4 = c & 15;
                *reinterpret_cast<uint2*>(base + row * SSTR + col4 * 4) =
                    quant4(v[j], qs);
            }
        }
    };

    float acc[4][8][4];
    #pragma unroll
    for (int a = 0; a < 4; a++)
        #pragma unroll
        for (int b = 0; b < 8; b++)
            #pragma unroll
            for (int c = 0; c < 4; c++) acc[a][b][c] = 0.f;

    const int warpM = wid & 1;
    const int warpN = (wid >> 1) & 1;
    const int mbase = warpM * 64;
    const int nbase = warpN * 64;

    const int arow = mbase + (lane & 15);
    const int acolx = (lane >> 4) << 3;
    const int brow = nbase + (lane & 7) + ((lane >> 4) << 3);
    const int bcolx = ((lane >> 3) & 1) << 3;

    const int kTiles = K / BKE;

    // ---- prologue ----
    if (QA == 0) {
        issueAB(0, 0);
        issueAB(1, 1);
    } else {
        if (wid == 4) {
            produceA(0, 0);
            produceA(1, 1);
        } else {
            issueB(0, 0);
            issueB(1, 1);
        }
        __syncthreads();   // A(0), A(1) visible to consumers
    }

    for (int kt = 0; kt < kTiles; kt++) {
        asm volatile("cp.async.wait_group 1;\n");   // no-op for producer warp
        __syncthreads();

        const int st  = kt % 3;
        const int st2 = (kt + 2) % 3;

        if (QA == 0) {
            if (kt + 2 < kTiles) issueAB(kt + 2, st2);
            else asm volatile("cp.async.commit_group;\n");
        } else {
            if (wid == 4) {
                if (kt + 2 < kTiles) produceA(kt + 2, st2);
            } else {
                if (kt + 2 < kTiles) issueB(kt + 2, st2);
                else asm volatile("cp.async.commit_group;\n");
            }
        }

        if (QA == 0 || wid < 4) {
            const __nv_bfloat16* bA = sm + st * STAGE_E;
            const __nv_bfloat16* bB = bA + A_ROWS * SSTR;

            #pragma unroll
            for (int ks = 0; ks < 4; ks++) {
                const int k0 = ks * 16;
                uint32_t af[4][4], bfm[4][4];
                #pragma unroll
                for (int mt = 0; mt < 4; mt++) {
                    unsigned addr = smem_u32(bA + (arow + mt * 16) * SSTR + k0 + acolx);
                    asm volatile(
                        "ldmatrix.sync.aligned.m8n8.x4.shared.b16 {%0,%1,%2,%3}, [%4];"
                        : "=r"(af[mt][0]), "=r"(af[mt][1]), "=r"(af[mt][2]), "=r"(af[mt][3])
                        : "r"(addr));
                }
                #pragma unroll
                for (int np = 0; np < 4; np++) {
                    unsigned addr = smem_u32(bB + (brow + np * 16) * SSTR + k0 + bcolx);
                    asm volatile(
                        "ldmatrix.sync.aligned.m8n8.x4.shared.b16 {%0,%1,%2,%3}, [%4];"
                        : "=r"(bfm[np][0]), "=r"(bfm[np][1]), "=r"(bfm[np][2]), "=r"(bfm[np][3])
                        : "r"(addr));
                }
                #pragma unroll
                for (int mt = 0; mt < 4; mt++)
                    #pragma unroll
                    for (int nt = 0; nt < 8; nt++) {
                        uint32_t b0 = bfm[nt >> 1][(nt & 1) * 2 + 0];
                        uint32_t b1 = bfm[nt >> 1][(nt & 1) * 2 + 1];
                        asm volatile(
                            "mma.sync.aligned.m16n8k16.row.col.f32.bf16.bf16.f32 "
                            "{%0,%1,%2,%3}, {%4,%5,%6,%7}, {%8,%9}, {%0,%1,%2,%3};"
                            : "+f"(acc[mt][nt][0]), "+f"(acc[mt][nt][1]),
                              "+f"(acc[mt][nt][2]), "+f"(acc[mt][nt][3])
                            : "r"(af[mt][0]), "r"(af[mt][1]), "r"(af[mt][2]), "r"(af[mt][3]),
                              "r"(b0), "r"(b1));
                    }
            }
        }
    }

    // ---------------- epilogue (mma warps only) ----------------
    if (QA == 0 || wid < 4) {
        const int gid = lane >> 2;
        const int tig = lane & 3;
        float amax_local = 0.f;

        #pragma unroll
        for (int mt = 0; mt < 4; mt++) {
            #pragma unroll
            for (int nt = 0; nt < 8; nt++) {
                int row0 = bm + mbase + mt * 16 + gid;
                int col0 = bn + nbase + nt * 8 + tig * 2;
                float bv0 = bias[col0];
                float bv1 = bias[col0 + 1];
                #pragma unroll
                for (int hh = 0; hh < 2; hh++) {
                    int row = row0 + hh * 8;
                    float v0 = acc[mt][nt][hh * 2 + 0] * cf + bv0;
                    float v1 = acc[mt][nt][hh * 2 + 1] * cf + bv1;
                    if (EPI == 1) {
                        v0 = gelu_exact(v0);
                        v1 = gelu_exact(v1);
                        amax_local = fmaxf(amax_local, fmaxf(fabsf(v0), fabsf(v1)));
                    }
                    *reinterpret_cast<float2*>(&C[(size_t)row * N + col0]) =
                        make_float2(v0, v1);
                }
            }
        }

        if (EPI == 1) {
            #pragma unroll
            for (int o = 16; o; o >>= 1)
                amax_local = fmaxf(amax_local, __shfl_xor_sync(0xffffffffu, amax_local, o));
            if (lane == 0) sred[wid] = amax_local;
            __syncthreads();
            if (tid == 0) {
                float m = fmaxf(fmaxf(sred[0], sred[1]), fmaxf(sred[2], sred[3]));
                atomicMax(amax_out, __float_as_uint(m));
            }
        }
    }
}

// ---------------- launch ----------------
extern "C" void kernel_launch(void* const* d_in, const int* in_sizes, int n_in,
                              void* d_out, int out_size) {
    const float* x  = (const float*)d_in[0];
    const float* W1 = (const float*)d_in[1];
    const float* b1 = (const float*)d_in[2];
    const float* W2 = (const float*)d_in[3];
    const float* b2 = (const float*)d_in[4];
    float* out = (float*)d_out;

    void *p_sc, *p_qx, *p_w1t, *p_h, *p_w2t;
    cudaGetSymbolAddress(&p_sc,  g_sc);
    cudaGetSymbolAddress(&p_qx,  g_qx);
    cudaGetSymbolAddress(&p_w1t, g_w1t);
    cudaGetSymbolAddress(&p_h,   g_h);
    cudaGetSymbolAddress(&p_w2t, g_w2t);
    Scalars* sc = (Scalars*)p_sc;

    cudaFuncSetAttribute(k_gemm<1,0>, cudaFuncAttributeMaxDynamicSharedMemorySize, SMEM_GB);
    cudaFuncSetAttribute(k_gemm<0,1>, cudaFuncAttributeMaxDynamicSharedMemorySize, SMEM_GB);

    cudaMemsetAsync(p_sc, 0, sizeof(Scalars));

    const int n4_xw = TOKENS * DMODEL / 4;               // 4,194,304

    // fused reductions: absmax(x), abssum(W1), abssum(W2)
    k_reduce3<<<dim3(1024, 3), 256>>>((const float4*)x, (const float4*)W1,
                                      (const float4*)W2, n4_xw, sc);

    // fused quant/ternarize: x->qx, W1->w1t, W2->w2t
    k_prep3<<<dim3(1024, 3), 256>>>((const float4*)x, (const float4*)W1,
                                    (const float4*)W2,
                                    (uint2*)p_qx, (uint2*)p_w1t, (uint2*)p_w2t,
                                    n4_xw, sc);

    // GEMM1: [8192 x 8192], K=2048, GELU epilogue -> h (fp32), amax_h (R12 path)
    dim3 g1(DFF / 128, TOKENS / 128);      // (64, 64) = 4096 CTAs
    k_gemm<1,0><<<g1, 128, SMEM_GB>>>(p_qx, (const __nv_bfloat16*)p_w1t,
                                      b1, (float*)p_h, TOKENS, DFF, DMODEL,
                                      &sc->sum_w1, &sc->absmax_x, &sc->absmax_h);

    // GEMM2: [8192 x 2048], K=8192 -> out (f32); A = fp32 h, quantized by
    // the producer warp inside the kernel (quant_h kernel eliminated).
    dim3 g2(DMODEL / 128, TOKENS / 128);   // (16, 64) = 1024 CTAs
    k_gemm<0,1><<<g2, 160, SMEM_GB>>>(p_h, (const __nv_bfloat16*)p_w2t,
                                      b2, out, TOKENS, DMODEL, DFF,
                                      &sc->sum_w2, &sc->absmax_h, nullptr);
}

// round 16
// speedup vs baseline: 4.8729x; 4.8729x over previous
#include <cuda_runtime.h>
#include <cuda_bf16.h>
#include <cstdint>

#define TOKENS 8192
#define DMODEL 2048
#define DFF    8192

// ---------------- device scratch (no allocations allowed) ----------------
struct Scalars {
    unsigned int absmax_x;   // float bits, >= 0
    unsigned int absmax_h;
    double       sum_w1;
    double       sum_w2;
};

__device__ Scalars        g_sc;
__device__ __nv_bfloat16  g_qx [(size_t)TOKENS * DMODEL];   // 32 MB
__device__ __nv_bfloat16  g_w1t[(size_t)DFF    * DMODEL];   // 32 MB
__device__ float          g_h  [(size_t)TOKENS * DFF];      // 256 MB (fp32 h — exact)
__device__ __nv_bfloat16  g_qh [(size_t)TOKENS * DFF];      // 128 MB
__device__ __nv_bfloat16  g_w2t[(size_t)DMODEL * DFF];      // 32 MB

// ---------------- helpers ----------------
__device__ __forceinline__ float gelu_exact(float v) {
    return 0.5f * v * (1.0f + erff(v * 0.70710678118654752440f));
}
__device__ __forceinline__ unsigned smem_u32(const void* p) {
    return (unsigned)__cvta_generic_to_shared(p);
}
__device__ __forceinline__ float amax4(float4 v) {
    return fmaxf(fmaxf(fabsf(v.x), fabsf(v.y)), fmaxf(fabsf(v.z), fabsf(v.w)));
}
__device__ __forceinline__ double asum4(float4 v) {
    return (double)fabsf(v.x) + (double)fabsf(v.y) +
           (double)fabsf(v.z) + (double)fabsf(v.w);
}
__device__ __forceinline__ uint2 quant4(float4 v, float s) {
    float q0 = rintf(fminf(fmaxf(v.x * s, -127.f), 127.f));
    float q1 = rintf(fminf(fmaxf(v.y * s, -127.f), 127.f));
    float q2 = rintf(fminf(fmaxf(v.z * s, -127.f), 127.f));
    float q3 = rintf(fminf(fmaxf(v.w * s, -127.f), 127.f));
    __nv_bfloat162 p0 = __floats2bfloat162_rn(q0, q1);
    __nv_bfloat162 p1 = __floats2bfloat162_rn(q2, q3);
    uint2 o;
    o.x = *reinterpret_cast<unsigned int*>(&p0);
    o.y = *reinterpret_cast<unsigned int*>(&p1);
    return o;
}
__device__ __forceinline__ uint2 tern4(float4 v, float inv) {
    float q0 = rintf(fminf(fmaxf(v.x * inv, -1.f), 1.f));
    float q1 = rintf(fminf(fmaxf(v.y * inv, -1.f), 1.f));
    float q2 = rintf(fminf(fmaxf(v.z * inv, -1.f), 1.f));
    float q3 = rintf(fminf(fmaxf(v.w * inv, -1.f), 1.f));
    __nv_bfloat162 p0 = __floats2bfloat162_rn(q0, q1);
    __nv_bfloat162 p1 = __floats2bfloat162_rn(q2, q3);
    uint2 o;
    o.x = *reinterpret_cast<unsigned int*>(&p0);
    o.y = *reinterpret_cast<unsigned int*>(&p1);
    return o;
}

// ---------------- fused reductions: seg0 absmax(x), seg1 abssum(W1), seg2 abssum(W2)
__global__ void k_reduce3(const float4* __restrict__ x,
                          const float4* __restrict__ W1,
                          const float4* __restrict__ W2,
                          int n4, Scalars* __restrict__ sc) {
    const int seg = blockIdx.y;
    const float4* p = (seg == 0) ? x : (seg == 1) ? W1 : W2;
    const int S = gridDim.x * blockDim.x;
    int i = blockIdx.x * blockDim.x + threadIdx.x;

    if (seg == 0) {
        float m = 0.f;
        for (; i + 3 * S < n4; i += 4 * S) {
            float4 v0 = p[i], v1 = p[i + S], v2 = p[i + 2 * S], v3 = p[i + 3 * S];
            m = fmaxf(m, fmaxf(fmaxf(amax4(v0), amax4(v1)),
                               fmaxf(amax4(v2), amax4(v3))));
        }
        for (; i < n4; i += S) m = fmaxf(m, amax4(p[i]));
        #pragma unroll
        for (int o = 16; o; o >>= 1) m = fmaxf(m, __shfl_xor_sync(0xffffffffu, m, o));
        __shared__ float s[8];
        if ((threadIdx.x & 31) == 0) s[threadIdx.x >> 5] = m;
        __syncthreads();
        if (threadIdx.x == 0) {
            float v = s[0];
            #pragma unroll
            for (int k = 1; k < 8; k++) v = fmaxf(v, s[k]);
            atomicMax(&sc->absmax_x, __float_as_uint(v));
        }
    } else {
        double acc = 0.0;
        for (; i + 3 * S < n4; i += 4 * S) {
            float4 v0 = p[i], v1 = p[i + S], v2 = p[i + 2 * S], v3 = p[i + 3 * S];
            acc += asum4(v0) + asum4(v1) + asum4(v2) + asum4(v3);
        }
        for (; i < n4; i += S) acc += asum4(p[i]);
        #pragma unroll
        for (int o = 16; o; o >>= 1) acc += __shfl_xor_sync(0xffffffffu, acc, o);
        __shared__ double sd[8];
        if ((threadIdx.x & 31) == 0) sd[threadIdx.x >> 5] = acc;
        __syncthreads();
        if (threadIdx.x == 0) {
            double v = sd[0];
            #pragma unroll
            for (int k = 1; k < 8; k++) v += sd[k];
            atomicAdd((seg == 1) ? &sc->sum_w1 : &sc->sum_w2, v);
        }
    }
}

// ---------------- fused prep: seg0 quant(x)->qx, seg1 tern(W1)->w1t, seg2 tern(W2)->w2t
__global__ void k_prep3(const float4* __restrict__ x,
                        const float4* __restrict__ W1,
                        const float4* __restrict__ W2,
                        uint2* __restrict__ qx,
                        uint2* __restrict__ w1t,
                        uint2* __restrict__ w2t,
                        int n4, const Scalars* __restrict__ sc) {
    const int seg = blockIdx.y;
    const float4* in = (seg == 0) ? x : (seg == 1) ? W1 : W2;
    uint2* out = (seg == 0) ? qx : (seg == 1) ? w1t : w2t;
    float s;
    if (seg == 0) s = 127.0f / __uint_as_float(sc->absmax_x);
    else {
        double sum = (seg == 1) ? sc->sum_w1 : sc->sum_w2;
        s = 1.0f / (float)(sum * (1.0 / 16777216.0));
    }
    const int S = gridDim.x * blockDim.x;
    int i = blockIdx.x * blockDim.x + threadIdx.x;
    if (seg == 0) {
        for (; i + 3 * S < n4; i += 4 * S) {
            float4 v0 = in[i], v1 = in[i + S], v2 = in[i + 2 * S], v3 = in[i + 3 * S];
            out[i] = quant4(v0, s);  out[i + S] = quant4(v1, s);
            out[i + 2 * S] = quant4(v2, s);  out[i + 3 * S] = quant4(v3, s);
        }
        for (; i < n4; i += S) out[i] = quant4(in[i], s);
    } else {
        for (; i + 3 * S < n4; i += 4 * S) {
            float4 v0 = in[i], v1 = in[i + S], v2 = in[i + 2 * S], v3 = in[i + 3 * S];
            out[i] = tern4(v0, s);  out[i + S] = tern4(v1, s);
            out[i + 2 * S] = tern4(v2, s);  out[i + 3 * S] = tern4(v3, s);
        }
        for (; i < n4; i += S) out[i] = tern4(in[i], s);
    }
}

// ---------------- quantize h (fp32) -> qh (bf16 ints), 4-way ILP ----------------
__global__ void k_quant_h(const float4* __restrict__ in, uint2* __restrict__ out,
                          int n4, const Scalars* __restrict__ sc) {
    float s = 127.0f / __uint_as_float(sc->absmax_h);
    const int S = gridDim.x * blockDim.x;
    int i = blockIdx.x * blockDim.x + threadIdx.x;
    for (; i + 3 * S < n4; i += 4 * S) {
        float4 v0 = __ldcs(&in[i]);
        float4 v1 = __ldcs(&in[i + S]);
        float4 v2 = __ldcs(&in[i + 2 * S]);
        float4 v3 = __ldcs(&in[i + 3 * S]);
        out[i] = quant4(v0, s);  out[i + S] = quant4(v1, s);
        out[i + 2 * S] = quant4(v2, s);  out[i + 3 * S] = quant4(v3, s);
    }
    for (; i < n4; i += S) out[i] = quant4(__ldcs(&in[i]), s);
}

// ---------------- bf16 GEMM: C[M,N] = A[M,K] @ B[N,K]^T ----------------
// CTA tile 128x128, BK=64, 128 threads (4 warps, 2(M) x 2(N), warp tile 64x64)
// 3-stage cp.async pipeline, 2 CTAs/SM. mma.sync.m16n8k16 bf16/f32.
// (R12 configuration — measured best: 1650.7 us.)
#define BKE     64                  // K elems per stage
#define SSTR    72                  // smem row stride (elems) = 144 B
#define A_ROWS  128
#define B_ROWS  128
#define STAGE_E ((A_ROWS + B_ROWS) * SSTR)   // 18432 elems
#define STAGES  3
#define SMEM_GB (STAGES * STAGE_E * 2)       // 110592 B
#define GTHREADS 128

template <int EPI>   // 1: *cf+bias, GELU, f32 store h, amax | 0: *cf+bias, f32 store
__global__ void __launch_bounds__(GTHREADS, 2) k_gemm(
    const __nv_bfloat16* __restrict__ A,
    const __nv_bfloat16* __restrict__ B,
    const float* __restrict__ bias,
    float* __restrict__ C,
    int M, int N, int K,
    const double* __restrict__ sump,
    const unsigned int* __restrict__ mxp,
    unsigned int* __restrict__ amax_out)
{
    extern __shared__ __nv_bfloat16 sm[];
    __shared__ float sred[4];

    const int tid  = threadIdx.x;
    const int wid  = tid >> 5;
    const int lane = tid & 31;
    const int bm = blockIdx.y * 128;
    const int bn = blockIdx.x * 128;

    const float cf = (float)(*sump * (1.0 / 16777216.0)) *
                     (__uint_as_float(*mxp) / 127.0f);

    const __nv_bfloat16* gA = A + (size_t)bm * K;
    const __nv_bfloat16* gB = B + (size_t)bn * K;

    // 16 x 16B cp.async per thread per stage (A: 1024 chunks, B: 1024 chunks)
    auto issue = [&](int kt, int st) {
        const int k0 = kt * BKE;
        __nv_bfloat16* base = sm + st * STAGE_E;
        #pragma unroll
        for (int i = 0; i < 16; i++) {
            int c = (i & 7) * GTHREADS + tid;
            int row = c >> 3, col = (c & 7) * 8;
            const __nv_bfloat16* src;
            __nv_bfloat16* dst;
            if (i < 8) {
                dst = base + row * SSTR + col;
                src = gA + (size_t)row * K + k0 + col;
            } else {
                dst = base + A_ROWS * SSTR + row * SSTR + col;
                src = gB + (size_t)row * K + k0 + col;
            }
            asm volatile("cp.async.cg.shared.global [%0], [%1], 16;\n"
                         :: "r"(smem_u32(dst)), "l"(src));
        }
        asm volatile("cp.async.commit_group;\n");
    };

    float acc[4][8][4];
    #pragma unroll
    for (int a = 0; a < 4; a++)
        #pragma unroll
        for (int b = 0; b < 8; b++)
            #pragma unroll
            for (int c = 0; c < 4; c++) acc[a][b][c] = 0.f;

    const int warpM = wid & 1;
    const int warpN = wid >> 1;
    const int mbase = warpM * 64;
    const int nbase = warpN * 64;

    const int kTiles = K / BKE;
    issue(0, 0);
    issue(1, 1);

    for (int kt = 0; kt < kTiles; kt++) {
        asm volatile("cp.async.wait_group 1;\n");
        __syncthreads();
        if (kt + 2 < kTiles) issue(kt + 2, (kt + 2) % 3);
        else asm volatile("cp.async.commit_group;\n");

        const int st = kt % 3;
        const __nv_bfloat16* bA = sm + st * STAGE_E;
        const __nv_bfloat16* bB = bA + A_ROWS * SSTR;

        #pragma unroll
        for (int ks = 0; ks < 4; ks++) {
            const int k0 = ks * 16;
            uint32_t af[4][4], bfm[4][4];
            #pragma unroll
            for (int mt = 0; mt < 4; mt++) {
                int r  = mbase + mt * 16 + (lane & 15);
                int cc = k0 + ((lane >> 4) << 3);
                unsigned addr = smem_u32(bA + r * SSTR + cc);
                asm volatile(
                    "ldmatrix.sync.aligned.m8n8.x4.shared.b16 {%0,%1,%2,%3}, [%4];"
                    : "=r"(af[mt][0]), "=r"(af[mt][1]), "=r"(af[mt][2]), "=r"(af[mt][3])
                    : "r"(addr));
            }
            #pragma unroll
            for (int np = 0; np < 4; np++) {
                int r  = nbase + np * 16 + (lane & 7) + ((lane >> 4) << 3);
                int cc = k0 + (((lane >> 3) & 1) << 3);
                unsigned addr = smem_u32(bB + r * SSTR + cc);
                asm volatile(
                    "ldmatrix.sync.aligned.m8n8.x4.shared.b16 {%0,%1,%2,%3}, [%4];"
                    : "=r"(bfm[np][0]), "=r"(bfm[np][1]), "=r"(bfm[np][2]), "=r"(bfm[np][3])
                    : "r"(addr));
            }
            #pragma unroll
            for (int mt = 0; mt < 4; mt++)
                #pragma unroll
                for (int nt = 0; nt < 8; nt++) {
                    uint32_t b0 = bfm[nt >> 1][(nt & 1) * 2 + 0];
                    uint32_t b1 = bfm[nt >> 1][(nt & 1) * 2 + 1];
                    asm volatile(
                        "mma.sync.aligned.m16n8k16.row.col.f32.bf16.bf16.f32 "
                        "{%0,%1,%2,%3}, {%4,%5,%6,%7}, {%8,%9}, {%0,%1,%2,%3};"
                        : "+f"(acc[mt][nt][0]), "+f"(acc[mt][nt][1]),
                          "+f"(acc[mt][nt][2]), "+f"(acc[mt][nt][3])
                        : "r"(af[mt][0]), "r"(af[mt][1]), "r"(af[mt][2]), "r"(af[mt][3]),
                          "r"(b0), "r"(b1));
                }
        }
    }

    // ---------------- epilogue ----------------
    const int gid = lane >> 2;
    const int tig = lane & 3;
    float amax_local = 0.f;

    #pragma unroll
    for (int mt = 0; mt < 4; mt++) {
        #pragma unroll
        for (int nt = 0; nt < 8; nt++) {
            int row0 = bm + mbase + mt * 16 + gid;
            int col0 = bn + nbase + nt * 8 + tig * 2;
            float bv0 = bias[col0];
            float bv1 = bias[col0 + 1];
            #pragma unroll
            for (int hh = 0; hh < 2; hh++) {
                int row = row0 + hh * 8;
                float v0 = acc[mt][nt][hh * 2 + 0] * cf + bv0;
                float v1 = acc[mt][nt][hh * 2 + 1] * cf + bv1;
                if (EPI == 1) {
                    v0 = gelu_exact(v0);
                    v1 = gelu_exact(v1);
                    amax_local = fmaxf(amax_local, fmaxf(fabsf(v0), fabsf(v1)));
                }
                *reinterpret_cast<float2*>(&C[(size_t)row * N + col0]) =
                    make_float2(v0, v1);
            }
        }
    }

    if (EPI == 1) {
        #pragma unroll
        for (int o = 16; o; o >>= 1)
            amax_local = fmaxf(amax_local, __shfl_xor_sync(0xffffffffu, amax_local, o));
        if (lane == 0) sred[wid] = amax_local;
        __syncthreads();
        if (tid == 0) {
            float m = fmaxf(fmaxf(sred[0], sred[1]), fmaxf(sred[2], sred[3]));
            atomicMax(amax_out, __float_as_uint(m));
        }
    }
}

// ---------------- launch ----------------
extern "C" void kernel_launch(void* const* d_in, const int* in_sizes, int n_in,
                              void* d_out, int out_size) {
    const float* x  = (const float*)d_in[0];
    const float* W1 = (const float*)d_in[1];
    const float* b1 = (const float*)d_in[2];
    const float* W2 = (const float*)d_in[3];
    const float* b2 = (const float*)d_in[4];
    float* out = (float*)d_out;

    void *p_sc, *p_qx, *p_w1t, *p_h, *p_qh, *p_w2t;
    cudaGetSymbolAddress(&p_sc,  g_sc);
    cudaGetSymbolAddress(&p_qx,  g_qx);
    cudaGetSymbolAddress(&p_w1t, g_w1t);
    cudaGetSymbolAddress(&p_h,   g_h);
    cudaGetSymbolAddress(&p_qh,  g_qh);
    cudaGetSymbolAddress(&p_w2t, g_w2t);
    Scalars* sc = (Scalars*)p_sc;

    cudaFuncSetAttribute(k_gemm<1>, cudaFuncAttributeMaxDynamicSharedMemorySize, SMEM_GB);
    cudaFuncSetAttribute(k_gemm<0>, cudaFuncAttributeMaxDynamicSharedMemorySize, SMEM_GB);

    cudaMemsetAsync(p_sc, 0, sizeof(Scalars));

    const int n4_xw = TOKENS * DMODEL / 4;               // 4,194,304
    const int n4_h  = (int)((size_t)TOKENS * DFF / 4);   // 16,777,216

    // fused reductions: absmax(x), abssum(W1), abssum(W2)
    k_reduce3<<<dim3(1024, 3), 256>>>((const float4*)x, (const float4*)W1,
                                      (const float4*)W2, n4_xw, sc);

    // fused quant/ternarize: x->qx, W1->w1t, W2->w2t
    k_prep3<<<dim3(1024, 3), 256>>>((const float4*)x, (const float4*)W1,
                                    (const float4*)W2,
                                    (uint2*)p_qx, (uint2*)p_w1t, (uint2*)p_w2t,
                                    n4_xw, sc);

    // GEMM1: [8192 x 8192], K=2048, GELU epilogue -> h (fp32), amax_h
    dim3 g1(DFF / 128, TOKENS / 128);      // (64, 64) = 4096 CTAs
    k_gemm<1><<<g1, GTHREADS, SMEM_GB>>>((const __nv_bfloat16*)p_qx,
                                         (const __nv_bfloat16*)p_w1t,
                                         b1, (float*)p_h, TOKENS, DFF, DMODEL,
                                         &sc->sum_w1, &sc->absmax_x, &sc->absmax_h);

    k_quant_h<<<6144, 256>>>((const float4*)p_h, (uint2*)p_qh, n4_h, sc);

    // GEMM2: [8192 x 2048], K=8192 -> out (f32)
    dim3 g2(DMODEL / 128, TOKENS / 128);   // (16, 64) = 1024 CTAs
    k_gemm<0><<<g2, GTHREADS, SMEM_GB>>>((const __nv_bfloat16*)p_qh,
                                         (const __nv_bfloat16*)p_w2t,
                                         b2, out, TOKENS, DMODEL, DFF,
                                         &sc->sum_w2, &sc->absmax_h, nullptr);
}

// round 17
// speedup vs baseline: 4.8973x; 1.0050x over previous
#include <cuda_runtime.h>
#include <cuda_bf16.h>
#include <cstdint>

#define TOKENS 8192
#define DMODEL 2048
#define DFF    8192

// ---------------- device scratch (no allocations allowed) ----------------
struct Scalars {
    unsigned int absmax_x;   // float bits, >= 0
    unsigned int absmax_h;
    double       sum_w1;
    double       sum_w2;
};

__device__ Scalars        g_sc;
__device__ __nv_bfloat16  g_qx [(size_t)TOKENS * DMODEL];   // 32 MB
__device__ __nv_bfloat16  g_w1t[(size_t)DFF    * DMODEL];   // 32 MB
__device__ float          g_h  [(size_t)TOKENS * DFF];      // 256 MB (fp32 h — exact)
__device__ __nv_bfloat16  g_qh [(size_t)TOKENS * DFF];      // 128 MB
__device__ __nv_bfloat16  g_w2t[(size_t)DMODEL * DFF];      // 32 MB

// ---------------- helpers ----------------
__device__ __forceinline__ float gelu_exact(float v) {
    return 0.5f * v * (1.0f + erff(v * 0.70710678118654752440f));
}
__device__ __forceinline__ unsigned smem_u32(const void* p) {
    return (unsigned)__cvta_generic_to_shared(p);
}
__device__ __forceinline__ float amax4(float4 v) {
    return fmaxf(fmaxf(fabsf(v.x), fabsf(v.y)), fmaxf(fabsf(v.z), fabsf(v.w)));
}
__device__ __forceinline__ double asum4(float4 v) {
    return (double)fabsf(v.x) + (double)fabsf(v.y) +
           (double)fabsf(v.z) + (double)fabsf(v.w);
}
__device__ __forceinline__ uint2 quant4(float4 v, float s) {
    float q0 = rintf(fminf(fmaxf(v.x * s, -127.f), 127.f));
    float q1 = rintf(fminf(fmaxf(v.y * s, -127.f), 127.f));
    float q2 = rintf(fminf(fmaxf(v.z * s, -127.f), 127.f));
    float q3 = rintf(fminf(fmaxf(v.w * s, -127.f), 127.f));
    __nv_bfloat162 p0 = __floats2bfloat162_rn(q0, q1);
    __nv_bfloat162 p1 = __floats2bfloat162_rn(q2, q3);
    uint2 o;
    o.x = *reinterpret_cast<unsigned int*>(&p0);
    o.y = *reinterpret_cast<unsigned int*>(&p1);
    return o;
}
__device__ __forceinline__ uint2 tern4(float4 v, float inv) {
    float q0 = rintf(fminf(fmaxf(v.x * inv, -1.f), 1.f));
    float q1 = rintf(fminf(fmaxf(v.y * inv, -1.f), 1.f));
    float q2 = rintf(fminf(fmaxf(v.z * inv, -1.f), 1.f));
    float q3 = rintf(fminf(fmaxf(v.w * inv, -1.f), 1.f));
    __nv_bfloat162 p0 = __floats2bfloat162_rn(q0, q1);
    __nv_bfloat162 p1 = __floats2bfloat162_rn(q2, q3);
    uint2 o;
    o.x = *reinterpret_cast<unsigned int*>(&p0);
    o.y = *reinterpret_cast<unsigned int*>(&p1);
    return o;
}

// ---------------- fused reductions: seg0 absmax(x), seg1 abssum(W1), seg2 abssum(W2)
__global__ void k_reduce3(const float4* __restrict__ x,
                          const float4* __restrict__ W1,
                          const float4* __restrict__ W2,
                          int n4, Scalars* __restrict__ sc) {
    const int seg = blockIdx.y;
    const float4* p = (seg == 0) ? x : (seg == 1) ? W1 : W2;
    const int S = gridDim.x * blockDim.x;
    int i = blockIdx.x * blockDim.x + threadIdx.x;

    if (seg == 0) {
        float m = 0.f;
        for (; i + 3 * S < n4; i += 4 * S) {
            float4 v0 = p[i], v1 = p[i + S], v2 = p[i + 2 * S], v3 = p[i + 3 * S];
            m = fmaxf(m, fmaxf(fmaxf(amax4(v0), amax4(v1)),
                               fmaxf(amax4(v2), amax4(v3))));
        }
        for (; i < n4; i += S) m = fmaxf(m, amax4(p[i]));
        #pragma unroll
        for (int o = 16; o; o >>= 1) m = fmaxf(m, __shfl_xor_sync(0xffffffffu, m, o));
        __shared__ float s[8];
        if ((threadIdx.x & 31) == 0) s[threadIdx.x >> 5] = m;
        __syncthreads();
        if (threadIdx.x == 0) {
            float v = s[0];
            #pragma unroll
            for (int k = 1; k < 8; k++) v = fmaxf(v, s[k]);
            atomicMax(&sc->absmax_x, __float_as_uint(v));
        }
    } else {
        double acc = 0.0;
        for (; i + 3 * S < n4; i += 4 * S) {
            float4 v0 = p[i], v1 = p[i + S], v2 = p[i + 2 * S], v3 = p[i + 3 * S];
            acc += asum4(v0) + asum4(v1) + asum4(v2) + asum4(v3);
        }
        for (; i < n4; i += S) acc += asum4(p[i]);
        #pragma unroll
        for (int o = 16; o; o >>= 1) acc += __shfl_xor_sync(0xffffffffu, acc, o);
        __shared__ double sd[8];
        if ((threadIdx.x & 31) == 0) sd[threadIdx.x >> 5] = acc;
        __syncthreads();
        if (threadIdx.x == 0) {
            double v = sd[0];
            #pragma unroll
            for (int k = 1; k < 8; k++) v += sd[k];
            atomicAdd((seg == 1) ? &sc->sum_w1 : &sc->sum_w2, v);
        }
    }
}

// ---------------- fused prep: seg0 quant(x)->qx, seg1 tern(W1)->w1t, seg2 tern(W2)->w2t
__global__ void k_prep3(const float4* __restrict__ x,
                        const float4* __restrict__ W1,
                        const float4* __restrict__ W2,
                        uint2* __restrict__ qx,
                        uint2* __restrict__ w1t,
                        uint2* __restrict__ w2t,
                        int n4, const Scalars* __restrict__ sc) {
    const int seg = blockIdx.y;
    const float4* in = (seg == 0) ? x : (seg == 1) ? W1 : W2;
    uint2* out = (seg == 0) ? qx : (seg == 1) ? w1t : w2t;
    float s;
    if (seg == 0) s = 127.0f / __uint_as_float(sc->absmax_x);
    else {
        double sum = (seg == 1) ? sc->sum_w1 : sc->sum_w2;
        s = 1.0f / (float)(sum * (1.0 / 16777216.0));
    }
    const int S = gridDim.x * blockDim.x;
    int i = blockIdx.x * blockDim.x + threadIdx.x;
    if (seg == 0) {
        for (; i + 3 * S < n4; i += 4 * S) {
            float4 v0 = in[i], v1 = in[i + S], v2 = in[i + 2 * S], v3 = in[i + 3 * S];
            out[i] = quant4(v0, s);  out[i + S] = quant4(v1, s);
            out[i + 2 * S] = quant4(v2, s);  out[i + 3 * S] = quant4(v3, s);
        }
        for (; i < n4; i += S) out[i] = quant4(in[i], s);
    } else {
        for (; i + 3 * S < n4; i += 4 * S) {
            float4 v0 = in[i], v1 = in[i + S], v2 = in[i + 2 * S], v3 = in[i + 3 * S];
            out[i] = tern4(v0, s);  out[i + S] = tern4(v1, s);
            out[i + 2 * S] = tern4(v2, s);  out[i + 3 * S] = tern4(v3, s);
        }
        for (; i < n4; i += S) out[i] = tern4(in[i], s);
    }
}

// ---------------- quantize h (fp32) -> qh (bf16 ints), 4-way ILP ----------------
__global__ void k_quant_h(const float4* __restrict__ in, uint2* __restrict__ out,
                          int n4, const Scalars* __restrict__ sc) {
    float s = 127.0f / __uint_as_float(sc->absmax_h);
    const int S = gridDim.x * blockDim.x;
    int i = blockIdx.x * blockDim.x + threadIdx.x;
    for (; i + 3 * S < n4; i += 4 * S) {
        float4 v0 = in[i], v1 = in[i + S], v2 = in[i + 2 * S], v3 = in[i + 3 * S];
        out[i] = quant4(v0, s);  out[i + S] = quant4(v1, s);
        out[i + 2 * S] = quant4(v2, s);  out[i + 3 * S] = quant4(v3, s);
    }
    for (; i < n4; i += S) out[i] = quant4(in[i], s);
}

// ---------------- bf16 GEMM: C[M,N] = A[M,K] @ B[N,K]^T ----------------
// CTA tile 128x128, BK=64, 128 threads (4 warps, 2(M) x 2(N), warp tile 64x64)
// 3-stage cp.async pipeline, 2 CTAs/SM. mma.sync.m16n8k16 bf16/f32.
// (R12 configuration — measured best: 1650.7 us.)
#define BKE     64                  // K elems per stage
#define SSTR    72                  // smem row stride (elems) = 144 B
#define A_ROWS  128
#define B_ROWS  128
#define STAGE_E ((A_ROWS + B_ROWS) * SSTR)   // 18432 elems
#define STAGES  3
#define SMEM_GB (STAGES * STAGE_E * 2)       // 110592 B
#define GTHREADS 128

template <int EPI>   // 1: *cf+bias, GELU, f32 store h, amax | 0: *cf+bias, f32 store
__global__ void __launch_bounds__(GTHREADS, 2) k_gemm(
    const __nv_bfloat16* __restrict__ A,
    const __nv_bfloat16* __restrict__ B,
    const float* __restrict__ bias,
    float* __restrict__ C,
    int M, int N, int K,
    const double* __restrict__ sump,
    const unsigned int* __restrict__ mxp,
    unsigned int* __restrict__ amax_out)
{
    extern __shared__ __nv_bfloat16 sm[];
    __shared__ float sred[4];

    const int tid  = threadIdx.x;
    const int wid  = tid >> 5;
    const int lane = tid & 31;
    const int bm = blockIdx.y * 128;
    const int bn = blockIdx.x * 128;

    const float cf = (float)(*sump * (1.0 / 16777216.0)) *
                     (__uint_as_float(*mxp) / 127.0f);

    const __nv_bfloat16* gA = A + (size_t)bm * K;
    const __nv_bfloat16* gB = B + (size_t)bn * K;

    // 16 x 16B cp.async per thread per stage (A: 1024 chunks, B: 1024 chunks)
    auto issue = [&](int kt, int st) {
        const int k0 = kt * BKE;
        __nv_bfloat16* base = sm + st * STAGE_E;
        #pragma unroll
        for (int i = 0; i < 16; i++) {
            int c = (i & 7) * GTHREADS + tid;
            int row = c >> 3, col = (c & 7) * 8;
            const __nv_bfloat16* src;
            __nv_bfloat16* dst;
            if (i < 8) {
                dst = base + row * SSTR + col;
                src = gA + (size_t)row * K + k0 + col;
            } else {
                dst = base + A_ROWS * SSTR + row * SSTR + col;
                src = gB + (size_t)row * K + k0 + col;
            }
            asm volatile("cp.async.cg.shared.global [%0], [%1], 16;\n"
                         :: "r"(smem_u32(dst)), "l"(src));
        }
        asm volatile("cp.async.commit_group;\n");
    };

    float acc[4][8][4];
    #pragma unroll
    for (int a = 0; a < 4; a++)
        #pragma unroll
        for (int b = 0; b < 8; b++)
            #pragma unroll
            for (int c = 0; c < 4; c++) acc[a][b][c] = 0.f;

    const int warpM = wid & 1;
    const int warpN = wid >> 1;
    const int mbase = warpM * 64;
    const int nbase = warpN * 64;

    const int kTiles = K / BKE;
    issue(0, 0);
    issue(1, 1);

    for (int kt = 0; kt < kTiles; kt++) {
        asm volatile("cp.async.wait_group 1;\n");
        __syncthreads();
        if (kt + 2 < kTiles) issue(kt + 2, (kt + 2) % 3);
        else asm volatile("cp.async.commit_group;\n");

        const int st = kt % 3;
        const __nv_bfloat16* bA = sm + st * STAGE_E;
        const __nv_bfloat16* bB = bA + A_ROWS * SSTR;

        #pragma unroll
        for (int ks = 0; ks < 4; ks++) {
            const int k0 = ks * 16;
            uint32_t af[4][4], bfm[4][4];
            #pragma unroll
            for (int mt = 0; mt < 4; mt++) {
                int r  = mbase + mt * 16 + (lane & 15);
                int cc = k0 + ((lane >> 4) << 3);
                unsigned addr = smem_u32(bA + r * SSTR + cc);
                asm volatile(
                    "ldmatrix.sync.aligned.m8n8.x4.shared.b16 {%0,%1,%2,%3}, [%4];"
                    : "=r"(af[mt][0]), "=r"(af[mt][1]), "=r"(af[mt][2]), "=r"(af[mt][3])
                    : "r"(addr));
            }
            #pragma unroll
            for (int np = 0; np < 4; np++) {
                int r  = nbase + np * 16 + (lane & 7) + ((lane >> 4) << 3);
                int cc = k0 + (((lane >> 3) & 1) << 3);
                unsigned addr = smem_u32(bB + r * SSTR + cc);
                asm volatile(
                    "ldmatrix.sync.aligned.m8n8.x4.shared.b16 {%0,%1,%2,%3}, [%4];"
                    : "=r"(bfm[np][0]), "=r"(bfm[np][1]), "=r"(bfm[np][2]), "=r"(bfm[np][3])
                    : "r"(addr));
            }
            #pragma unroll
            for (int mt = 0; mt < 4; mt++)
                #pragma unroll
                for (int nt = 0; nt < 8; nt++) {
                    uint32_t b0 = bfm[nt >> 1][(nt & 1) * 2 + 0];
                    uint32_t b1 = bfm[nt >> 1][(nt & 1) * 2 + 1];
                    asm volatile(
                        "mma.sync.aligned.m16n8k16.row.col.f32.bf16.bf16.f32 "
                        "{%0,%1,%2,%3}, {%4,%5,%6,%7}, {%8,%9}, {%0,%1,%2,%3};"
                        : "+f"(acc[mt][nt][0]), "+f"(acc[mt][nt][1]),
                          "+f"(acc[mt][nt][2]), "+f"(acc[mt][nt][3])
                        : "r"(af[mt][0]), "r"(af[mt][1]), "r"(af[mt][2]), "r"(af[mt][3]),
                          "r"(b0), "r"(b1));
                }
        }
    }

    // ---------------- epilogue ----------------
    const int gid = lane >> 2;
    const int tig = lane & 3;
    float amax_local = 0.f;

    #pragma unroll
    for (int mt = 0; mt < 4; mt++) {
        #pragma unroll
        for (int nt = 0; nt < 8; nt++) {
            int row0 = bm + mbase + mt * 16 + gid;
            int col0 = bn + nbase + nt * 8 + tig * 2;
            float bv0 = bias[col0];
            float bv1 = bias[col0 + 1];
            #pragma unroll
            for (int hh = 0; hh < 2; hh++) {
                int row = row0 + hh * 8;
                float v0 = acc[mt][nt][hh * 2 + 0] * cf + bv0;
                float v1 = acc[mt][nt][hh * 2 + 1] * cf + bv1;
                if (EPI == 1) {
                    v0 = gelu_exact(v0);
                    v1 = gelu_exact(v1);
                    amax_local = fmaxf(amax_local, fmaxf(fabsf(v0), fabsf(v1)));
                }
                *reinterpret_cast<float2*>(&C[(size_t)row * N + col0]) =
                    make_float2(v0, v1);
            }
        }
    }

    if (EPI == 1) {
        #pragma unroll
        for (int o = 16; o; o >>= 1)
            amax_local = fmaxf(amax_local, __shfl_xor_sync(0xffffffffu, amax_local, o));
        if (lane == 0) sred[wid] = amax_local;
        __syncthreads();
        if (tid == 0) {
            float m = fmaxf(fmaxf(sred[0], sred[1]), fmaxf(sred[2], sred[3]));
            atomicMax(amax_out, __float_as_uint(m));
        }
    }
}

// ---------------- launch ----------------
extern "C" void kernel_launch(void* const* d_in, const int* in_sizes, int n_in,
                              void* d_out, int out_size) {
    const float* x  = (const float*)d_in[0];
    const float* W1 = (const float*)d_in[1];
    const float* b1 = (const float*)d_in[2];
    const float* W2 = (const float*)d_in[3];
    const float* b2 = (const float*)d_in[4];
    float* out = (float*)d_out;

    void *p_sc, *p_qx, *p_w1t, *p_h, *p_qh, *p_w2t;
    cudaGetSymbolAddress(&p_sc,  g_sc);
    cudaGetSymbolAddress(&p_qx,  g_qx);
    cudaGetSymbolAddress(&p_w1t, g_w1t);
    cudaGetSymbolAddress(&p_h,   g_h);
    cudaGetSymbolAddress(&p_qh,  g_qh);
    cudaGetSymbolAddress(&p_w2t, g_w2t);
    Scalars* sc = (Scalars*)p_sc;

    cudaFuncSetAttribute(k_gemm<1>, cudaFuncAttributeMaxDynamicSharedMemorySize, SMEM_GB);
    cudaFuncSetAttribute(k_gemm<0>, cudaFuncAttributeMaxDynamicSharedMemorySize, SMEM_GB);

    cudaMemsetAsync(p_sc, 0, sizeof(Scalars));

    const int n4_xw = TOKENS * DMODEL / 4;               // 4,194,304
    const int n4_h  = (int)((size_t)TOKENS * DFF / 4);   // 16,777,216

    // fused reductions: absmax(x), abssum(W1), abssum(W2)
    k_reduce3<<<dim3(1024, 3), 256>>>((const float4*)x, (const float4*)W1,
                                      (const float4*)W2, n4_xw, sc);

    // fused quant/ternarize: x->qx, W1->w1t, W2->w2t
    k_prep3<<<dim3(1024, 3), 256>>>((const float4*)x, (const float4*)W1,
                                    (const float4*)W2,
                                    (uint2*)p_qx, (uint2*)p_w1t, (uint2*)p_w2t,
                                    n4_xw, sc);

    // GEMM1: [8192 x 8192], K=2048, GELU epilogue -> h (fp32), amax_h
    dim3 g1(DFF / 128, TOKENS / 128);      // (64, 64) = 4096 CTAs
    k_gemm<1><<<g1, GTHREADS, SMEM_GB>>>((const __nv_bfloat16*)p_qx,
                                         (const __nv_bfloat16*)p_w1t,
                                         b1, (float*)p_h, TOKENS, DFF, DMODEL,
                                         &sc->sum_w1, &sc->absmax_x, &sc->absmax_h);

    k_quant_h<<<4096, 256>>>((const float4*)p_h, (uint2*)p_qh, n4_h, sc);

    // GEMM2: [8192 x 2048], K=8192 -> out (f32)
    dim3 g2(DMODEL / 128, TOKENS / 128);   // (16, 64) = 1024 CTAs
    k_gemm<0><<<g2, GTHREADS, SMEM_GB>>>((const __nv_bfloat16*)p_qh,
                                         (const __nv_bfloat16*)p_w2t,
                                         b2, out, TOKENS, DMODEL, DFF,
                                         &sc->sum_w2, &sc->absmax_h, nullptr);
}